// round 1
// baseline (speedup 1.0000x reference)
#include <cuda_runtime.h>
#include <cooperative_groups.h>
#include <math.h>

namespace cg = cooperative_groups;

#define B_   256
#define T_   256
#define D_   128
#define H_   256
#define R_   (B_ * T_)        // 65536 rows (b,t)
#define KU   384              // packed input width: [x_imp(128), m(128), Delta(128)]
#define CW   1024             // packed output width: [A_z(256), A_r(256), A_h(256), dh(256)]
#define NB   8                // batches per cluster
#define WPAD 260              // padded k-stride in recurrence smem (bank spread)

// ---------------- scratch (static device allocations; no runtime alloc) ----------------
__device__ float g_U[(size_t)R_ * KU];       // 96 MB  packed inputs
__device__ float g_S[(size_t)R_ * CW];       // 256 MB precomputed A_z/A_r/A_h/delta_h
__device__ float g_Wp[CW * KU];              // packed precompute weights [col][k]
__device__ float g_bp[CW];                   // packed biases
__device__ float g_WT[3 * H_ * H_];          // recurrent weights [g][j][k] = W_g[j][128+k]
__device__ float g_Hfin[B_ * H_];            // final hidden state

// ---------------- kernel 0: pack weights ----------------
__global__ void pack_kernel(const float* __restrict__ Wz, const float* __restrict__ bz,
                            const float* __restrict__ Wr, const float* __restrict__ br,
                            const float* __restrict__ Wh, const float* __restrict__ bh,
                            const float* __restrict__ Wgh, const float* __restrict__ bgh) {
    int idx = blockIdx.x * blockDim.x + threadIdx.x;
    if (idx < CW * KU) {
        int col = idx / KU, k = idx - col * KU;
        int g = col >> 8, j = col & 255;
        float v = 0.f;
        if (g < 3) {
            const float* W = (g == 0) ? Wz : ((g == 1) ? Wr : Wh);
            if (k < 128)      v = W[j * 512 + k];            // x part (comb cols 0..127)
            else if (k < 256) v = W[j * 512 + 256 + k];      // m part (comb cols 384..511)
        } else {
            if (k >= 256) v = Wgh[j * 128 + (k - 256)];      // Delta part
        }
        g_Wp[idx] = v;
    }
    if (idx < CW) {
        int g = idx >> 8, j = idx & 255;
        g_bp[idx] = (g == 0) ? bz[j] : (g == 1) ? br[j] : (g == 2) ? bh[j] : bgh[j];
    }
    if (idx < 3 * H_ * H_) {
        int g = idx >> 16;
        int rem = idx & 65535;
        int j = rem >> 8, k = rem & 255;
        const float* W = (g == 0) ? Wz : ((g == 1) ? Wr : Wh);
        g_WT[idx] = W[j * 512 + 128 + k];                    // h part (comb cols 128..383)
    }
}

// ---------------- kernel 1: imputation + input packing ----------------
__global__ void build_U(const float* __restrict__ inp, const float* __restrict__ Xmean,
                        const float* __restrict__ Wgx, const float* __restrict__ bgx) {
    int idx = blockIdx.x * blockDim.x + threadIdx.x;
    if (idx >= R_ * D_) return;
    int d = idx & 127;
    int r = idx >> 7;
    int t = r & 255;
    int b = r >> 8;
    size_t TD = (size_t)T_ * D_;
    size_t base = (size_t)b * 4 * TD + (size_t)t * D_ + d;
    float x  = inp[base];
    float xl = inp[base + TD];
    float m  = inp[base + 2 * TD];
    float dl = inp[base + 3 * TD];
    float a   = dl * Wgx[d * D_ + d] + bgx[d];
    float dxt = expf(-fmaxf(a, 0.f));
    if (isnan(x)) x = -1.f;
    float xi = m * x + (1.f - m) * (dxt * xl + (1.f - dxt) * Xmean[t * D_ + d]);
    float* Urow = g_U + (size_t)r * KU;
    Urow[d]       = xi;
    Urow[128 + d] = m;
    Urow[256 + d] = dl;
}

// ---------------- kernel 2: precompute GEMM  S = U @ Wp^T (+bias, dh activation) ----------------
__global__ __launch_bounds__(256) void gemm_pre() {
    const int c0 = blockIdx.x * 64;     // col tile (gate-aligned: 64 | 256)
    const int r0 = blockIdx.y * 64;     // row tile
    const int gate   = c0 >> 8;
    const int kstart = (gate < 3) ? 0 : 256;
    const int ktiles = (gate < 3) ? 8 : 4;
    __shared__ float Us[64][36];
    __shared__ float Ws[64][36];
    const int tid = threadIdx.x;
    const int tx = tid & 15;
    const int ty = tid >> 4;
    const int lrow = tid >> 3;
    const int lk   = (tid & 7) << 2;
    float acc[4][4];
#pragma unroll
    for (int d = 0; d < 4; d++)
#pragma unroll
        for (int e = 0; e < 4; e++) acc[d][e] = 0.f;

    for (int kt = 0; kt < ktiles; kt++) {
        int kb = kstart + kt * 32;
        *(float4*)&Us[lrow][lk]    = *(const float4*)&g_U[(size_t)(r0 + lrow) * KU + kb + lk];
        *(float4*)&Us[lrow+32][lk] = *(const float4*)&g_U[(size_t)(r0 + lrow + 32) * KU + kb + lk];
        *(float4*)&Ws[lrow][lk]    = *(const float4*)&g_Wp[(size_t)(c0 + lrow) * KU + kb + lk];
        *(float4*)&Ws[lrow+32][lk] = *(const float4*)&g_Wp[(size_t)(c0 + lrow + 32) * KU + kb + lk];
        __syncthreads();
#pragma unroll
        for (int k = 0; k < 32; k++) {
            float a0 = Us[ty][k],      a1 = Us[ty + 16][k];
            float a2 = Us[ty + 32][k], a3 = Us[ty + 48][k];
            float w0 = Ws[tx][k],      w1 = Ws[tx + 16][k];
            float w2 = Ws[tx + 32][k], w3 = Ws[tx + 48][k];
            acc[0][0] = fmaf(a0, w0, acc[0][0]); acc[0][1] = fmaf(a0, w1, acc[0][1]);
            acc[0][2] = fmaf(a0, w2, acc[0][2]); acc[0][3] = fmaf(a0, w3, acc[0][3]);
            acc[1][0] = fmaf(a1, w0, acc[1][0]); acc[1][1] = fmaf(a1, w1, acc[1][1]);
            acc[1][2] = fmaf(a1, w2, acc[1][2]); acc[1][3] = fmaf(a1, w3, acc[1][3]);
            acc[2][0] = fmaf(a2, w0, acc[2][0]); acc[2][1] = fmaf(a2, w1, acc[2][1]);
            acc[2][2] = fmaf(a2, w2, acc[2][2]); acc[2][3] = fmaf(a2, w3, acc[2][3]);
            acc[3][0] = fmaf(a3, w0, acc[3][0]); acc[3][1] = fmaf(a3, w1, acc[3][1]);
            acc[3][2] = fmaf(a3, w2, acc[3][2]); acc[3][3] = fmaf(a3, w3, acc[3][3]);
        }
        __syncthreads();
    }
#pragma unroll
    for (int e = 0; e < 4; e++) {
        int col = c0 + tx + 16 * e;
        float bias = g_bp[col];
#pragma unroll
        for (int d = 0; d < 4; d++) {
            int row = r0 + ty + 16 * d;
            float v = acc[d][e] + bias;
            if (gate == 3) v = expf(-fmaxf(v, 0.f));   // delta_h activation
            g_S[(size_t)row * CW + col] = v;
        }
    }
}

// ---------------- kernel 3: recurrence (4-CTA cluster, resident fp32 weights) ----------------
__global__ void __cluster_dims__(4, 1, 1) __launch_bounds__(256, 1) recur_kernel() {
    extern __shared__ float smem[];
    float* Wq     = smem;                       // [3][64][WPAD]  = 195 KB
    float* hfull  = Wq + 3 * 64 * WPAD;         // [NB][WPAD]
    float* rhfull = hfull + NB * WPAD;          // [NB][WPAD]

    cg::cluster_group cluster = cg::this_cluster();
    const int rank  = (int)cluster.block_rank();   // 0..3, owns j in [rank*64, rank*64+64)
    const int tid   = threadIdx.x;
    const int jl    = tid >> 2;                    // 0..63
    const int bg    = tid & 3;                     // 0..3
    const int b0    = bg, b1 = bg + 4;             // local batch indices (NB=8)
    const int jg    = rank * 64 + jl;              // global hidden index
    const int b_base = (blockIdx.x >> 2) * NB;     // global batch base of this cluster

    // Load this CTA's j-slice of all three recurrent matrices (coalesced; one-time)
    for (int idx = tid; idx < 3 * 64 * 256; idx += 256) {
        int g  = idx >> 14;
        int jj = (idx >> 8) & 63;
        int k  = idx & 255;
        Wq[g * (64 * WPAD) + jj * WPAD + k] = g_WT[g * 65536 + (rank * 64 + jj) * 256 + k];
    }
    for (int i = tid; i < NB * WPAD; i += 256) { hfull[i] = 0.f; rhfull[i] = 0.f; }
    __syncthreads();
    cluster.sync();

    const float* Wz_s = Wq;
    const float* Wr_s = Wq + 64 * WPAD;
    const float* Wh_s = Wq + 2 * 64 * WPAD;

    for (int t = 0; t < T_; t++) {
        size_t rb0 = ((size_t)(b_base + b0) * T_ + t) * CW;
        size_t rb1 = ((size_t)(b_base + b1) * T_ + t) * CW;
        // issue A-loads early (consumed after the matvecs -> latency hidden)
        float az0 = g_S[rb0 + jg],       az1 = g_S[rb1 + jg];
        float ar0 = g_S[rb0 + 256 + jg], ar1 = g_S[rb1 + 256 + jg];
        float ah0 = g_S[rb0 + 512 + jg], ah1 = g_S[rb1 + 512 + jg];

        // h <- delta_h(t) * h  (each CTA scales its full local copy)
#pragma unroll
        for (int q = 0; q < NB; q++) {
            int i  = tid + q * 256;
            int bb = i >> 8, k = i & 255;
            float dh = g_S[((size_t)(b_base + bb) * T_ + t) * CW + 768 + k];
            hfull[bb * WPAD + k] *= dh;
        }
        __syncthreads();

        // z / r matvecs over full h
        float accz0 = 0.f, accz1 = 0.f, accr0 = 0.f, accr1 = 0.f;
#pragma unroll 4
        for (int k = 0; k < 256; k += 4) {
            float4 wz = *(const float4*)&Wz_s[jl * WPAD + k];
            float4 wr = *(const float4*)&Wr_s[jl * WPAD + k];
            float4 h0 = *(const float4*)&hfull[b0 * WPAD + k];
            float4 h1 = *(const float4*)&hfull[b1 * WPAD + k];
            accz0 = fmaf(wz.x,h0.x, fmaf(wz.y,h0.y, fmaf(wz.z,h0.z, fmaf(wz.w,h0.w, accz0))));
            accz1 = fmaf(wz.x,h1.x, fmaf(wz.y,h1.y, fmaf(wz.z,h1.z, fmaf(wz.w,h1.w, accz1))));
            accr0 = fmaf(wr.x,h0.x, fmaf(wr.y,h0.y, fmaf(wr.z,h0.z, fmaf(wr.w,h0.w, accr0))));
            accr1 = fmaf(wr.x,h1.x, fmaf(wr.y,h1.y, fmaf(wr.z,h1.z, fmaf(wr.w,h1.w, accr1))));
        }
        float z0 = 1.f / (1.f + expf(-(accz0 + az0)));
        float z1 = 1.f / (1.f + expf(-(accz1 + az1)));
        float r0 = 1.f / (1.f + expf(-(accr0 + ar0)));
        float r1 = 1.f / (1.f + expf(-(accr1 + ar1)));

        float hj0 = hfull[b0 * WPAD + jg];
        float hj1 = hfull[b1 * WPAD + jg];
        float rh0 = r0 * hj0;
        float rh1 = r1 * hj1;
        // broadcast r*h quarter to all 4 CTAs (DSMEM)
#pragma unroll
        for (int pr = 0; pr < 4; pr++) {
            float* prh = cluster.map_shared_rank(rhfull, pr);
            prh[b0 * WPAD + jg] = rh0;
            prh[b1 * WPAD + jg] = rh1;
        }
        cluster.sync();

        // h_tilde matvec over full r*h
        float acch0 = 0.f, acch1 = 0.f;
#pragma unroll 4
        for (int k = 0; k < 256; k += 4) {
            float4 wh = *(const float4*)&Wh_s[jl * WPAD + k];
            float4 p0 = *(const float4*)&rhfull[b0 * WPAD + k];
            float4 p1 = *(const float4*)&rhfull[b1 * WPAD + k];
            acch0 = fmaf(wh.x,p0.x, fmaf(wh.y,p0.y, fmaf(wh.z,p0.z, fmaf(wh.w,p0.w, acch0))));
            acch1 = fmaf(wh.x,p1.x, fmaf(wh.y,p1.y, fmaf(wh.z,p1.z, fmaf(wh.w,p1.w, acch1))));
        }
        float ht0 = tanhf(acch0 + ah0);
        float ht1 = tanhf(acch1 + ah1);
        float hn0 = (1.f - z0) * hj0 + z0 * ht0;
        float hn1 = (1.f - z1) * hj1 + z1 * ht1;
        // broadcast new-h quarter to all 4 CTAs
#pragma unroll
        for (int pr = 0; pr < 4; pr++) {
            float* ph = cluster.map_shared_rank(hfull, pr);
            ph[b0 * WPAD + jg] = hn0;
            ph[b1 * WPAD + jg] = hn1;
        }
        cluster.sync();

        if (t == T_ - 1) {
            g_Hfin[(b_base + b0) * H_ + jg] = hn0;
            g_Hfin[(b_base + b1) * H_ + jg] = hn1;
        }
    }
}

// ---------------- kernel 4: out = h_final @ W_out^T + b_out ----------------
__global__ void finalize_k(const float* __restrict__ Wout, const float* __restrict__ bout,
                           float* __restrict__ out) {
    int b = blockIdx.x;
    int tid = threadIdx.x;   // 64 threads
    float s = 0.f;
    for (int j = tid; j < H_; j += 64) s += g_Hfin[b * H_ + j] * Wout[j];
    __shared__ float red[64];
    red[tid] = s;
    __syncthreads();
    if (tid < 32) {
        float v = red[tid] + red[tid + 32];
#pragma unroll
        for (int o = 16; o; o >>= 1) v += __shfl_down_sync(0xffffffffu, v, o);
        if (tid == 0) out[b] = v + bout[0];
    }
}

// ---------------- host launcher ----------------
extern "C" void kernel_launch(void* const* d_in, const int* in_sizes, int n_in,
                              void* d_out, int out_size) {
    const float* inp   = (const float*)d_in[0];
    // d_in[1] = static_data (unused by the reference computation)
    const float* Xmean = (const float*)d_in[2];
    const float* Wz    = (const float*)d_in[3];
    const float* bz    = (const float*)d_in[4];
    const float* Wr    = (const float*)d_in[5];
    const float* br    = (const float*)d_in[6];
    const float* Wh    = (const float*)d_in[7];
    const float* bh    = (const float*)d_in[8];
    const float* Wgx   = (const float*)d_in[9];
    const float* bgx   = (const float*)d_in[10];
    const float* Wgh   = (const float*)d_in[11];
    const float* bgh   = (const float*)d_in[12];
    const float* Wout  = (const float*)d_in[13];
    const float* bout  = (const float*)d_in[14];
    float* out = (float*)d_out;

    pack_kernel<<<(CW * KU + 255) / 256, 256>>>(Wz, bz, Wr, br, Wh, bh, Wgh, bgh);
    build_U<<<(R_ * D_ + 255) / 256, 256>>>(inp, Xmean, Wgx, bgx);

    dim3 g2(CW / 64, R_ / 64);   // 16 x 1024 tiles
    gemm_pre<<<g2, 256>>>();

    const int smemb = (3 * 64 * WPAD + 2 * NB * WPAD) * (int)sizeof(float);  // 216320 B
    cudaFuncSetAttribute(recur_kernel, cudaFuncAttributeMaxDynamicSharedMemorySize, smemb);
    recur_kernel<<<128, 256, smemb>>>();   // 32 clusters of 4 CTAs

    finalize_k<<<B_, 64>>>(Wout, bout, out);
}